// round 13
// baseline (speedup 1.0000x reference)
#include <cuda_runtime.h>
#include <cuda_fp16.h>
#include <cstdint>
#include <cstddef>

#define DEV __device__ __forceinline__

// ---------------- problem dims ----------------
constexpr int BATCH = 8192;
constexpr int FEAT  = 4096;
constexpr int Q     = 1024;

// ---------------- tiling ----------------
constexpr int BM = 128;
constexpr int BN = 128;
constexpr int BK = 128;                   // fp16 per k-tile (256B rows, 16 chunks)
constexpr int IT_PER_TILE = 48;           // 6 phases x 8 k-tiles
constexpr int NSTAGE = 3;

constexpr int A_TILE_BYTES = BM * BK * 2; // 32768
constexpr int B_TILE_BYTES = BN * BK * 2; // 32768
constexpr int OFF_B = A_TILE_BYTES;
constexpr int STAGE_BYTES = A_TILE_BYTES + B_TILE_BYTES;       // 65536

constexpr int SM_FULL  = 0;               // 3 x 8B
constexpr int SM_EMPTY = 64;              // 3 x 8B
constexpr int SM_DATA  = 1024;
constexpr int SMEM_TOTAL = SM_DATA + NSTAGE * STAGE_BYTES;     // 197632

constexpr int MT = BATCH / BM;            // 64
constexpr int NT = Q / BN;                // 8
constexpr int NTILES = 2 * MT * NT;       // 1024

// ---------------- device scratch ----------------
__device__ __half g_X[(size_t)6 * BATCH * Q];
__device__ __half g_W[(size_t)12 * Q * Q];

// ---------------- helpers ----------------
DEV uint32_t smem_u32(const void* p) {
    uint32_t a;
    asm("{ .reg .u64 t; cvta.to.shared.u64 t, %1; cvt.u32.u64 %0, t; }" : "=r"(a) : "l"(p));
    return a;
}
DEV void mbar_init(uint32_t a, uint32_t cnt) {
    asm volatile("mbarrier.init.shared.b64 [%0], %1;" :: "r"(a), "r"(cnt) : "memory");
}
DEV void mbar_expect_tx(uint32_t a, uint32_t bytes) {
    asm volatile("mbarrier.arrive.expect_tx.shared.b64 _, [%0], %1;"
                 :: "r"(a), "r"(bytes) : "memory");
}
DEV void mbar_arrive(uint32_t a) {
    asm volatile("mbarrier.arrive.shared.b64 _, [%0];" :: "r"(a) : "memory");
}
DEV void mbar_wait(uint32_t a, uint32_t parity) {
    asm volatile(
        "{\n\t.reg .pred P;\n\t"
        "WL%=:\n\t"
        "mbarrier.try_wait.parity.acquire.cta.shared::cta.b64 P, [%0], %1, 0x989680;\n\t"
        "@P bra.uni WD%=;\n\t"
        "bra.uni WL%=;\n\t"
        "WD%=:\n\t}"
        :: "r"(a), "r"(parity) : "memory");
}
// strictly non-blocking probe (test_wait) -> 1 if barrier phase complete
DEV uint32_t mbar_test(uint32_t a, uint32_t parity) {
    uint32_t done;
    asm volatile(
        "{\n\t.reg .pred p;\n\t"
        "mbarrier.test_wait.parity.acquire.cta.shared::cta.b64 p, [%1], %2;\n\t"
        "selp.b32 %0, 1, 0, p;\n\t}"
        : "=r"(done) : "r"(a), "r"(parity) : "memory");
    return done;
}
DEV void bulk_g2s(uint32_t dst, const void* src, uint32_t bytes, uint32_t mbar) {
    asm volatile(
        "cp.async.bulk.shared::cluster.global.mbarrier::complete_tx::bytes [%0], [%1], %2, [%3];"
        :: "r"(dst), "l"(src), "r"(bytes), "r"(mbar) : "memory");
}
DEV void ldsm4(uint32_t& r0, uint32_t& r1, uint32_t& r2, uint32_t& r3, uint32_t addr) {
    asm volatile("ldmatrix.sync.aligned.m8n8.x4.shared.b16 {%0,%1,%2,%3}, [%4];"
                 : "=r"(r0), "=r"(r1), "=r"(r2), "=r"(r3) : "r"(addr));
}
DEV void mma_f16(float* d, const uint32_t* a, const uint32_t* b) {
    asm volatile(
        "mma.sync.aligned.m16n8k16.row.col.f32.f16.f16.f32 "
        "{%0,%1,%2,%3}, {%4,%5,%6,%7}, {%8,%9}, {%0,%1,%2,%3};"
        : "+f"(d[0]), "+f"(d[1]), "+f"(d[2]), "+f"(d[3])
        : "r"(a[0]), "r"(a[1]), "r"(a[2]), "r"(a[3]), "r"(b[0]), "r"(b[1]));
}
DEV uint32_t pack2(float lo, float hi) {
    __half2 h = __halves2half2(__float2half_rn(lo), __float2half_rn(hi));
    return *reinterpret_cast<uint32_t*>(&h);
}
DEV void stcs2(float* p, float2 v) {
    asm volatile("st.global.cs.v2.f32 [%0], {%1, %2};" :: "l"(p), "f"(v.x), "f"(v.y) : "memory");
}

// ---------------- fused prep: blocks [0,4096) pack X (6 A-mats), [4096,4608) pack W ----
constexpr int XP_BLOCKS = (1 << 20) / 256;   // 4096
constexpr int WP_BLOCKS = (1 << 17) / 256;   // 512

__global__ void k_pack(const float* __restrict__ x,
                       const float* __restrict__ wrr, const float* __restrict__ wri,
                       const float* __restrict__ wrj, const float* __restrict__ wrk) {
    if (blockIdx.x < XP_BLOCKS) {
        size_t gci = (size_t)blockIdx.x * 256 + threadIdx.x;     // 2^20 chunk-slots
        int t  = (int)(gci >> 11);            // 0..511 = mt*8 + ktl
        int ci = (int)(gci & 2047);
        int mt = t >> 3, ktl = t & 7;
        int row = ci >> 4, c = ci & 15;
        const float* base = x + (size_t)(mt * 128 + row) * FEAT + ktl * 128 + c * 8;
        float4 v[4][2];
#pragma unroll
        for (int j = 0; j < 4; j++) {
            const float4* s = reinterpret_cast<const float4*>(base + j * Q);
            v[j][0] = s[0]; v[j][1] = s[1];
        }
        uint4 d[6];
#pragma unroll
        for (int j = 0; j < 4; j++) {
            d[j].x = pack2(v[j][0].x, v[j][0].y); d[j].y = pack2(v[j][0].z, v[j][0].w);
            d[j].z = pack2(v[j][1].x, v[j][1].y); d[j].w = pack2(v[j][1].z, v[j][1].w);
        }
        d[4].x = pack2(v[0][0].x + v[1][0].x, v[0][0].y + v[1][0].y);
        d[4].y = pack2(v[0][0].z + v[1][0].z, v[0][0].w + v[1][0].w);
        d[4].z = pack2(v[0][1].x + v[1][1].x, v[0][1].y + v[1][1].y);
        d[4].w = pack2(v[0][1].z + v[1][1].z, v[0][1].w + v[1][1].w);
        d[5].x = pack2(v[2][0].x + v[3][0].x, v[2][0].y + v[3][0].y);
        d[5].y = pack2(v[2][0].z + v[3][0].z, v[2][0].w + v[3][0].w);
        d[5].z = pack2(v[2][1].x + v[3][1].x, v[2][1].y + v[3][1].y);
        d[5].w = pack2(v[2][1].z + v[3][1].z, v[2][1].w + v[3][1].w);
        size_t dstbase = ((size_t)t << 11) + (row << 4) + (c ^ (row & 7));
        uint4* o = reinterpret_cast<uint4*>(g_X);
#pragma unroll
        for (int j = 0; j < 6; j++) o[((size_t)j << 20) + dstbase] = d[j];
    } else {
        int gci = (blockIdx.x - XP_BLOCKS) * 256 + threadIdx.x;   // 2^17 chunk positions
        int t  = gci >> 11;                   // 0..63 = nt*8 + ktl
        int ci = gci & 2047;
        int row = ci >> 4, c = ci & 15;
        int o = (t >> 3) * 128 + row;
        int k = (t & 7) * 128 + c * 8;
        size_t off = (size_t)o * Q + k;
        const float* srcs[4] = {wrr, wri, wrj, wrk};
        float f[4][8];
#pragma unroll
        for (int m = 0; m < 4; m++) {
            const float4* s = reinterpret_cast<const float4*>(srcs[m] + off);
            float4 v0 = s[0], v1 = s[1];
            f[m][0] = v0.x; f[m][1] = v0.y; f[m][2] = v0.z; f[m][3] = v0.w;
            f[m][4] = v1.x; f[m][5] = v1.y; f[m][6] = v1.z; f[m][7] = v1.w;
        }
        // combos:           0    1    2    3    4      5      6    7    8    9    10     11
        //                  Wrr -Wrj  Wri  Wrk rr+ri  rk-rj   Wrj  Wrr  Wrk -Wri rj+rk  rr-ri
        constexpr int   s1[12] = {  0,   2,   1,   3,   0,   3,   2,   0,   3,   1,   2,   0 };
        constexpr float g1[12] = {  1,  -1,   1,   1,   1,   1,   1,   1,   1,  -1,   1,   1 };
        constexpr int   s2[12] = { -1,  -1,  -1,  -1,   1,   2,  -1,  -1,  -1,  -1,   3,   1 };
        constexpr float g2[12] = {  0,   0,   0,   0,   1,  -1,   0,   0,   0,   0,   1,  -1 };
        size_t dstbase = ((size_t)t << 11) + (row << 4) + (c ^ (row & 7));
        uint4* outp = reinterpret_cast<uint4*>(g_W);
#pragma unroll
        for (int b = 0; b < 12; b++) {
            float v[8];
#pragma unroll
            for (int e = 0; e < 8; e++) {
                float xv = g1[b] * f[s1[b]][e];
                if (s2[b] >= 0) xv += g2[b] * f[s2[b]][e];
                v[e] = xv;
            }
            uint4 d;
            d.x = pack2(v[0], v[1]); d.y = pack2(v[2], v[3]);
            d.z = pack2(v[4], v[5]); d.w = pack2(v[6], v[7]);
            outp[((size_t)b << 17) + dstbase] = d;
        }
    }
}

// ---------------- main kernel: persistent, 288 threads ----------------
// warps 0-7: consumers (2M x 4N grid, warp tile 64x32); warp 8 lane 0: producer
__global__ void __launch_bounds__(288, 1)
k_qdense(const float* __restrict__ brr, float* __restrict__ out, int gsz) {
    extern __shared__ char smem[];
    uint32_t sb = smem_u32(smem);
    int tid = threadIdx.x, wid = tid >> 5, lane = tid & 31;
    int wm = wid >> 2, wn = wid & 3;
    int cta = blockIdx.x;

    if (cta >= NTILES) return;
    int ntiles = (NTILES - cta + gsz - 1) / gsz;
    int total_it = ntiles * IT_PER_TILE;

    if (tid == 0) {
#pragma unroll
        for (int s = 0; s < NSTAGE; s++) {
            mbar_init(sb + SM_FULL  + 8 * s, 1);   // expect_tx-driven
            mbar_init(sb + SM_EMPTY + 8 * s, 8);   // one arrive per consumer warp
        }
    }
    __syncthreads();

    // phase -> A matrix selector (nibble-packed): {0,2,1,3,4,5}
    const uint32_t ASEL = 0x543120u;

    // ---------------- producer warp (warp 8) ----------------
    if (wid == 8) {
        if (lane == 0) {
#pragma unroll 1
            for (int g = 0; g < total_it; g++) {
                int s = g % NSTAGE;
                mbar_wait(sb + SM_EMPTY + 8 * s, (uint32_t)(((g / NSTAGE) ^ 1) & 1));
                int tile = cta + (g / IT_PER_TILE) * gsz;
                int l = g % IT_PER_TILE;
                int ph = l >> 3, ktl = l & 7;
                int nt = tile & 7, mt = (tile >> 3) & 63, pc = tile >> 9;
                uint32_t a_sel = (ASEL >> (ph * 4)) & 0xF;
                const __half* sa = g_X + ((size_t)a_sel << 23) + ((size_t)(mt * 8 + ktl) << 14);
                const __half* sw = g_W + ((size_t)(pc * 6 + ph) << 20) + ((size_t)(nt * 8 + ktl) << 14);
                uint32_t mb = sb + SM_FULL + 8 * s;
                uint32_t st = sb + SM_DATA + s * STAGE_BYTES;
                mbar_expect_tx(mb, STAGE_BYTES);
                bulk_g2s(st,         sa, A_TILE_BYTES, mb);
                bulk_g2s(st + OFF_B, sw, B_TILE_BYTES, mb);
            }
        }
        return;
    }

    // ---------------- consumer warps ----------------
    float acc0[4][4][4], acc1[4][4][4];

    int a_rowl_base = ((lane >> 3) & 1) * 8 + (lane & 7);
    int a_chunk_sel = lane >> 4;
    int b_rowl_base = ((lane >> 4) << 3) + (lane & 7);
    int b_chunk_sel = (lane >> 3) & 1;

    auto load_frags = [&](uint32_t abase, uint32_t bbase, int ks,
                          uint32_t (*a)[4], uint32_t (*b)[2]) {
#pragma unroll
        for (int mf = 0; mf < 4; mf++) {
            int rowl = mf * 16 + a_rowl_base;
            int chunk = ks * 2 + a_chunk_sel;
            uint32_t addr = abase + rowl * 256 + ((chunk ^ (rowl & 7)) << 4);
            ldsm4(a[mf][0], a[mf][1], a[mf][2], a[mf][3], addr);
        }
#pragma unroll
        for (int nf2 = 0; nf2 < 2; nf2++) {
            int rowl = nf2 * 16 + b_rowl_base;
            int chunk = ks * 2 + b_chunk_sel;
            uint32_t addr = bbase + rowl * 256 + ((chunk ^ (rowl & 7)) << 4);
            ldsm4(b[2 * nf2][0], b[2 * nf2][1], b[2 * nf2 + 1][0], b[2 * nf2 + 1][1], addr);
        }
    };

    // do_kt: consume stage g into acc; 'ready' = probe result for g's full barrier.
    // Returns hidden probe result for g+1 (issued mid-loop).
    auto do_kt = [&](int g, float (*acc)[4][4], uint32_t ready) -> uint32_t {
        int s = g % NSTAGE;
        if (!ready) mbar_wait(sb + SM_FULL + 8 * s, (uint32_t)((g / NSTAGE) & 1));

        uint32_t abase = sb + SM_DATA + s * STAGE_BYTES + wm * (64 * 256);
        uint32_t bbase = sb + SM_DATA + s * STAGE_BYTES + OFF_B + wn * (32 * 256);

        int gn = g + 1;
        uint32_t mb_n = sb + SM_FULL + 8 * (gn % NSTAGE);
        uint32_t par_n = (uint32_t)((gn / NSTAGE) & 1);
        uint32_t ready_next = 0;

        uint32_t a[2][4][4], b[2][4][2];
        load_frags(abase, bbase, 0, a[0], b[0]);
#pragma unroll
        for (int ks = 0; ks < 8; ks++) {
            int cur = ks & 1;
            if (ks < 7) {
                load_frags(abase, bbase, ks + 1, a[cur ^ 1], b[cur ^ 1]);
            } else {
                if (lane == 0) mbar_arrive(sb + SM_EMPTY + 8 * s);   // stage reads all issued
            }
            if (ks == 4) ready_next = mbar_test(mb_n, par_n);        // hidden probe for g+1
#pragma unroll
            for (int mf = 0; mf < 4; mf++)
#pragma unroll
                for (int nf = 0; nf < 4; nf++)
                    mma_f16(acc[mf][nf], a[cur][mf], b[cur][nf]);
        }
        return ready_next;
    };

    int g = 0;
    uint32_t rdy = 0;
#pragma unroll 1
    for (int i = 0; i < ntiles; i++) {
        int tile = cta + i * gsz;
        int nt = tile & 7, mt = (tile >> 3) & 63, pc = tile >> 9;

#pragma unroll
        for (int ii = 0; ii < 4; ii++)
#pragma unroll
            for (int j = 0; j < 4; j++)
#pragma unroll
                for (int v = 0; v < 4; v++) { acc0[ii][j][v] = 0.0f; acc1[ii][j][v] = 0.0f; }

        // segment 0: phases 0,1 -> acc0 (accA)
#pragma unroll 1
        for (int l = 0; l < 16; l++) rdy = do_kt(g + l, acc0, rdy);
        // segment 1: phases 2,3 -> acc1 (accB)
#pragma unroll 1
        for (int l = 16; l < 32; l++) rdy = do_kt(g + l, acc1, rdy);

        float bia[4][2];
#pragma unroll
        for (int nf = 0; nf < 4; nf++) {
            int coll = wn * 32 + nf * 8 + (lane & 3) * 2;
            bia[nf][0] = __ldg(brr + nt * BN + coll);
            bia[nf][1] = __ldg(brr + nt * BN + coll + 1);
        }

        // mid epilogue: out_first = A - B + bias; then acc0 = A + B (T)
        {
            size_t colR = (size_t)pc * 2048 + nt * BN;
#pragma unroll
            for (int nf = 0; nf < 4; nf++) {
                int coll = wn * 32 + nf * 8 + (lane & 3) * 2;
#pragma unroll
                for (int mf = 0; mf < 4; mf++) {
                    size_t row0 = (size_t)mt * BM + wm * 64 + mf * 16 + (lane >> 2);
#pragma unroll
                    for (int h = 0; h < 2; h++) {
                        int v0 = h * 2, v1 = h * 2 + 1;
                        float2 vr = make_float2(acc0[mf][nf][v0] - acc1[mf][nf][v0] + bia[nf][0],
                                                acc0[mf][nf][v1] - acc1[mf][nf][v1] + bia[nf][1]);
                        stcs2(out + (row0 + h * 8) * FEAT + colR + coll, vr);
                    }
                }
            }
#pragma unroll
            for (int ii = 0; ii < 4; ii++)
#pragma unroll
                for (int j = 0; j < 4; j++)
#pragma unroll
                    for (int v = 0; v < 4; v++) {
                        acc0[ii][j][v] += acc1[ii][j][v];   // T = A + B
                        acc1[ii][j][v] = 0.0f;
                    }
        }

        // segment 2: phases 4,5 -> acc1 (accC)
#pragma unroll 1
        for (int l = 32; l < 48; l++) rdy = do_kt(g + l, acc1, rdy);

        // final epilogue: out_second = C - T + bias
        {
            size_t colR = (size_t)pc * 2048 + nt * BN + 1024;
#pragma unroll
            for (int nf = 0; nf < 4; nf++) {
                int coll = wn * 32 + nf * 8 + (lane & 3) * 2;
#pragma unroll
                for (int mf = 0; mf < 4; mf++) {
                    size_t row0 = (size_t)mt * BM + wm * 64 + mf * 16 + (lane >> 2);
#pragma unroll
                    for (int h = 0; h < 2; h++) {
                        int v0 = h * 2, v1 = h * 2 + 1;
                        float2 vi = make_float2(acc1[mf][nf][v0] - acc0[mf][nf][v0] + bia[nf][0],
                                                acc1[mf][nf][v1] - acc0[mf][nf][v1] + bia[nf][1]);
                        stcs2(out + (row0 + h * 8) * FEAT + colR + coll, vi);
                    }
                }
            }
        }
        g += IT_PER_TILE;
    }
}

// ---------------- launch ----------------
extern "C" void kernel_launch(void* const* d_in, const int* in_sizes, int n_in,
                              void* d_out, int out_size) {
    const float* x   = (const float*)d_in[0];
    const float* wrr = (const float*)d_in[1];
    const float* wri = (const float*)d_in[2];
    const float* wrj = (const float*)d_in[3];
    const float* wrk = (const float*)d_in[4];
    const float* brr = (const float*)d_in[5];
    float* out = (float*)d_out;

    k_pack<<<XP_BLOCKS + WP_BLOCKS, 256>>>(x, wrr, wri, wrj, wrk);

    static int g_sms = -1;
    if (g_sms < 0) {
        cudaDeviceProp prop;
        cudaGetDeviceProperties(&prop, 0);
        g_sms = prop.multiProcessorCount;
        cudaFuncSetAttribute(k_qdense, cudaFuncAttributeMaxDynamicSharedMemorySize, SMEM_TOTAL);
    }
    k_qdense<<<g_sms, 288, SMEM_TOTAL>>>(brr, out, g_sms);
}

// round 14
// speedup vs baseline: 1.0838x; 1.0838x over previous
#include <cuda_runtime.h>
#include <cuda_fp16.h>
#include <cstdint>
#include <cstddef>

#define DEV __device__ __forceinline__

// ---------------- problem dims ----------------
constexpr int BATCH = 8192;
constexpr int FEAT  = 4096;
constexpr int Q     = 1024;

// ---------------- tiling ----------------
constexpr int BM = 128;
constexpr int BN = 128;
constexpr int BK = 128;                   // fp16 per k-tile (256B rows, 16 chunks)
constexpr int IT_PER_TILE = 48;           // 6 phases x 8 k-tiles
constexpr int NSTAGE = 3;

constexpr int A_TILE_BYTES = BM * BK * 2; // 32768
constexpr int B_TILE_BYTES = BN * BK * 2; // 32768
constexpr int OFF_B = A_TILE_BYTES;
constexpr int STAGE_BYTES = A_TILE_BYTES + B_TILE_BYTES;       // 65536

constexpr int SM_FULL  = 0;               // 3 x 8B
constexpr int SM_EMPTY = 64;              // 3 x 8B
constexpr int SM_DATA  = 1024;
constexpr int SMEM_TOTAL = SM_DATA + NSTAGE * STAGE_BYTES;     // 197632

constexpr int MT = BATCH / BM;            // 64
constexpr int NT = Q / BN;                // 8
constexpr int NTILES = 2 * MT * NT;       // 1024

// ---------------- device scratch ----------------
__device__ __half g_X[(size_t)6 * BATCH * Q];
__device__ __half g_W[(size_t)12 * Q * Q];

// ---------------- helpers ----------------
DEV uint32_t smem_u32(const void* p) {
    uint32_t a;
    asm("{ .reg .u64 t; cvta.to.shared.u64 t, %1; cvt.u32.u64 %0, t; }" : "=r"(a) : "l"(p));
    return a;
}
DEV void mbar_init(uint32_t a, uint32_t cnt) {
    asm volatile("mbarrier.init.shared.b64 [%0], %1;" :: "r"(a), "r"(cnt) : "memory");
}
DEV void mbar_expect_tx(uint32_t a, uint32_t bytes) {
    asm volatile("mbarrier.arrive.expect_tx.shared.b64 _, [%0], %1;"
                 :: "r"(a), "r"(bytes) : "memory");
}
DEV void mbar_arrive(uint32_t a) {
    asm volatile("mbarrier.arrive.shared.b64 _, [%0];" :: "r"(a) : "memory");
}
DEV void mbar_wait(uint32_t a, uint32_t parity) {
    asm volatile(
        "{\n\t.reg .pred P;\n\t"
        "WL%=:\n\t"
        "mbarrier.try_wait.parity.acquire.cta.shared::cta.b64 P, [%0], %1, 0x989680;\n\t"
        "@P bra.uni WD%=;\n\t"
        "bra.uni WL%=;\n\t"
        "WD%=:\n\t}"
        :: "r"(a), "r"(parity) : "memory");
}
// strictly non-blocking probe (test_wait) -> 1 if barrier phase complete
DEV uint32_t mbar_test(uint32_t a, uint32_t parity) {
    uint32_t done;
    asm volatile(
        "{\n\t.reg .pred p;\n\t"
        "mbarrier.test_wait.parity.acquire.cta.shared::cta.b64 p, [%1], %2;\n\t"
        "selp.b32 %0, 1, 0, p;\n\t}"
        : "=r"(done) : "r"(a), "r"(parity) : "memory");
    return done;
}
DEV void bulk_g2s(uint32_t dst, const void* src, uint32_t bytes, uint32_t mbar) {
    asm volatile(
        "cp.async.bulk.shared::cluster.global.mbarrier::complete_tx::bytes [%0], [%1], %2, [%3];"
        :: "r"(dst), "l"(src), "r"(bytes), "r"(mbar) : "memory");
}
DEV void ldsm4(uint32_t& r0, uint32_t& r1, uint32_t& r2, uint32_t& r3, uint32_t addr) {
    asm volatile("ldmatrix.sync.aligned.m8n8.x4.shared.b16 {%0,%1,%2,%3}, [%4];"
                 : "=r"(r0), "=r"(r1), "=r"(r2), "=r"(r3) : "r"(addr));
}
DEV void mma_f16(float* d, const uint32_t* a, const uint32_t* b) {
    asm volatile(
        "mma.sync.aligned.m16n8k16.row.col.f32.f16.f16.f32 "
        "{%0,%1,%2,%3}, {%4,%5,%6,%7}, {%8,%9}, {%0,%1,%2,%3};"
        : "+f"(d[0]), "+f"(d[1]), "+f"(d[2]), "+f"(d[3])
        : "r"(a[0]), "r"(a[1]), "r"(a[2]), "r"(a[3]), "r"(b[0]), "r"(b[1]));
}
DEV uint32_t pack2(float lo, float hi) {
    __half2 h = __halves2half2(__float2half_rn(lo), __float2half_rn(hi));
    return *reinterpret_cast<uint32_t*>(&h);
}
DEV void stcs2(float* p, float2 v) {
    asm volatile("st.global.cs.v2.f32 [%0], {%1, %2};" :: "l"(p), "f"(v.x), "f"(v.y) : "memory");
}

// ---------------- fused prep: blocks [0,4096) pack X (6 A-mats), [4096,4608) pack W ----
constexpr int XP_BLOCKS = (1 << 20) / 256;   // 4096
constexpr int WP_BLOCKS = (1 << 17) / 256;   // 512

__global__ void k_pack(const float* __restrict__ x,
                       const float* __restrict__ wrr, const float* __restrict__ wri,
                       const float* __restrict__ wrj, const float* __restrict__ wrk) {
    if (blockIdx.x < XP_BLOCKS) {
        size_t gci = (size_t)blockIdx.x * 256 + threadIdx.x;     // 2^20 chunk-slots
        int t  = (int)(gci >> 11);            // 0..511 = mt*8 + ktl
        int ci = (int)(gci & 2047);
        int mt = t >> 3, ktl = t & 7;
        int row = ci >> 4, c = ci & 15;
        const float* base = x + (size_t)(mt * 128 + row) * FEAT + ktl * 128 + c * 8;
        float4 v[4][2];
#pragma unroll
        for (int j = 0; j < 4; j++) {
            const float4* s = reinterpret_cast<const float4*>(base + j * Q);
            v[j][0] = s[0]; v[j][1] = s[1];
        }
        uint4 d[6];
#pragma unroll
        for (int j = 0; j < 4; j++) {
            d[j].x = pack2(v[j][0].x, v[j][0].y); d[j].y = pack2(v[j][0].z, v[j][0].w);
            d[j].z = pack2(v[j][1].x, v[j][1].y); d[j].w = pack2(v[j][1].z, v[j][1].w);
        }
        d[4].x = pack2(v[0][0].x + v[1][0].x, v[0][0].y + v[1][0].y);
        d[4].y = pack2(v[0][0].z + v[1][0].z, v[0][0].w + v[1][0].w);
        d[4].z = pack2(v[0][1].x + v[1][1].x, v[0][1].y + v[1][1].y);
        d[4].w = pack2(v[0][1].z + v[1][1].z, v[0][1].w + v[1][1].w);
        d[5].x = pack2(v[2][0].x + v[3][0].x, v[2][0].y + v[3][0].y);
        d[5].y = pack2(v[2][0].z + v[3][0].z, v[2][0].w + v[3][0].w);
        d[5].z = pack2(v[2][1].x + v[3][1].x, v[2][1].y + v[3][1].y);
        d[5].w = pack2(v[2][1].z + v[3][1].z, v[2][1].w + v[3][1].w);
        size_t dstbase = ((size_t)t << 11) + (row << 4) + (c ^ (row & 7));
        uint4* o = reinterpret_cast<uint4*>(g_X);
#pragma unroll
        for (int j = 0; j < 6; j++) o[((size_t)j << 20) + dstbase] = d[j];
    } else {
        int gci = (blockIdx.x - XP_BLOCKS) * 256 + threadIdx.x;   // 2^17 chunk positions
        int t  = gci >> 11;                   // 0..63 = nt*8 + ktl
        int ci = gci & 2047;
        int row = ci >> 4, c = ci & 15;
        int o = (t >> 3) * 128 + row;
        int k = (t & 7) * 128 + c * 8;
        size_t off = (size_t)o * Q + k;
        const float* srcs[4] = {wrr, wri, wrj, wrk};
        float f[4][8];
#pragma unroll
        for (int m = 0; m < 4; m++) {
            const float4* s = reinterpret_cast<const float4*>(srcs[m] + off);
            float4 v0 = s[0], v1 = s[1];
            f[m][0] = v0.x; f[m][1] = v0.y; f[m][2] = v0.z; f[m][3] = v0.w;
            f[m][4] = v1.x; f[m][5] = v1.y; f[m][6] = v1.z; f[m][7] = v1.w;
        }
        // combos:           0    1    2    3    4      5      6    7    8    9    10     11
        //                  Wrr -Wrj  Wri  Wrk rr+ri  rk-rj   Wrj  Wrr  Wrk -Wri rj+rk  rr-ri
        constexpr int   s1[12] = {  0,   2,   1,   3,   0,   3,   2,   0,   3,   1,   2,   0 };
        constexpr float g1[12] = {  1,  -1,   1,   1,   1,   1,   1,   1,   1,  -1,   1,   1 };
        constexpr int   s2[12] = { -1,  -1,  -1,  -1,   1,   2,  -1,  -1,  -1,  -1,   3,   1 };
        constexpr float g2[12] = {  0,   0,   0,   0,   1,  -1,   0,   0,   0,   0,   1,  -1 };
        size_t dstbase = ((size_t)t << 11) + (row << 4) + (c ^ (row & 7));
        uint4* outp = reinterpret_cast<uint4*>(g_W);
#pragma unroll
        for (int b = 0; b < 12; b++) {
            float v[8];
#pragma unroll
            for (int e = 0; e < 8; e++) {
                float xv = g1[b] * f[s1[b]][e];
                if (s2[b] >= 0) xv += g2[b] * f[s2[b]][e];
                v[e] = xv;
            }
            uint4 d;
            d.x = pack2(v[0], v[1]); d.y = pack2(v[2], v[3]);
            d.z = pack2(v[4], v[5]); d.w = pack2(v[6], v[7]);
            outp[((size_t)b << 17) + dstbase] = d;
        }
    }
}

// ---------------- main kernel: persistent, 256 threads, 8 warps (2M x 4N) ----------------
__global__ void __launch_bounds__(256, 1)
k_qdense(const float* __restrict__ brr, float* __restrict__ out, int gsz) {
    extern __shared__ char smem[];
    uint32_t sb = smem_u32(smem);
    int tid = threadIdx.x, wid = tid >> 5, lane = tid & 31;
    int wm = wid >> 2, wn = wid & 3;
    int cta = blockIdx.x;

    if (cta >= NTILES) return;
    int ntiles = (NTILES - cta + gsz - 1) / gsz;
    int total_it = ntiles * IT_PER_TILE;

    if (tid == 0) {
#pragma unroll
        for (int s = 0; s < NSTAGE; s++) {
            mbar_init(sb + SM_FULL  + 8 * s, 1);   // expect_tx-driven
            mbar_init(sb + SM_EMPTY + 8 * s, 8);   // one arrive per warp
        }
    }
    __syncthreads();

    // phase -> A matrix selector (nibble-packed): {0,2,1,3,4,5}
    const uint32_t ASEL = 0x543120u;

    auto produce = [&](int g) {
        int s = g % NSTAGE;
        mbar_wait(sb + SM_EMPTY + 8 * s, (uint32_t)(((g / NSTAGE) ^ 1) & 1));
        int tile = cta + (g / IT_PER_TILE) * gsz;
        int l = g % IT_PER_TILE;
        int ph = l >> 3, ktl = l & 7;
        int nt = tile & 7, mt = (tile >> 3) & 63, pc = tile >> 9;
        uint32_t a_sel = (ASEL >> (ph * 4)) & 0xF;
        const __half* sa = g_X + ((size_t)a_sel << 23) + ((size_t)(mt * 8 + ktl) << 14);
        const __half* sw = g_W + ((size_t)(pc * 6 + ph) << 20) + ((size_t)(nt * 8 + ktl) << 14);
        uint32_t mb = sb + SM_FULL + 8 * s;
        uint32_t st = sb + SM_DATA + s * STAGE_BYTES;
        mbar_expect_tx(mb, STAGE_BYTES);
        bulk_g2s(st,         sa, A_TILE_BYTES, mb);
        bulk_g2s(st + OFF_B, sw, B_TILE_BYTES, mb);
    };

    if (tid == 0) { produce(0); produce(1); }

    float acc0[4][4][4], acc1[4][4][4];

    int a_rowl_base = ((lane >> 3) & 1) * 8 + (lane & 7);
    int a_chunk_sel = lane >> 4;
    int b_rowl_base = ((lane >> 4) << 3) + (lane & 7);
    int b_chunk_sel = (lane >> 3) & 1;

    auto load_frags = [&](uint32_t abase, uint32_t bbase, int ks,
                          uint32_t (*a)[4], uint32_t (*b)[2]) {
#pragma unroll
        for (int mf = 0; mf < 4; mf++) {
            int rowl = mf * 16 + a_rowl_base;
            int chunk = ks * 2 + a_chunk_sel;
            uint32_t addr = abase + rowl * 256 + ((chunk ^ (rowl & 7)) << 4);
            ldsm4(a[mf][0], a[mf][1], a[mf][2], a[mf][3], addr);
        }
#pragma unroll
        for (int nf2 = 0; nf2 < 2; nf2++) {
            int rowl = nf2 * 16 + b_rowl_base;
            int chunk = ks * 2 + b_chunk_sel;
            uint32_t addr = bbase + rowl * 256 + ((chunk ^ (rowl & 7)) << 4);
            ldsm4(b[2 * nf2][0], b[2 * nf2][1], b[2 * nf2 + 1][0], b[2 * nf2 + 1][1], addr);
        }
    };

    // do_kt: consume stage for iteration g into acc.
    // 'ready' = non-blocking probe result for g's full barrier (from previous kt).
    // Returns the probe result for g+1's full barrier (tested mid-loop, latency hidden).
    auto do_kt = [&](int g, float (*acc)[4][4], uint32_t ready) -> uint32_t {
        int s = g % NSTAGE;
        if (tid == 0 && g + 2 < total_it) produce(g + 2);
        if (!ready) mbar_wait(sb + SM_FULL + 8 * s, (uint32_t)((g / NSTAGE) & 1));

        uint32_t abase = sb + SM_DATA + s * STAGE_BYTES + wm * (64 * 256);
        uint32_t bbase = sb + SM_DATA + s * STAGE_BYTES + OFF_B + wn * (32 * 256);

        int gn = g + 1;
        uint32_t mb_n = sb + SM_FULL + 8 * (gn % NSTAGE);
        uint32_t par_n = (uint32_t)((gn / NSTAGE) & 1);
        uint32_t ready_next = 0;

        uint32_t a[2][4][4], b[2][4][2];
        load_frags(abase, bbase, 0, a[0], b[0]);
#pragma unroll
        for (int ks = 0; ks < 8; ks++) {
            int cur = ks & 1;
            if (ks < 7) {
                load_frags(abase, bbase, ks + 1, a[cur ^ 1], b[cur ^ 1]);
            } else {
                if (lane == 0) mbar_arrive(sb + SM_EMPTY + 8 * s);   // stage reads all issued
            }
            if (ks == 4) ready_next = mbar_test(mb_n, par_n);        // hidden probe for g+1
#pragma unroll
            for (int mf = 0; mf < 4; mf++)
#pragma unroll
                for (int nf = 0; nf < 4; nf++)
                    mma_f16(acc[mf][nf], a[cur][mf], b[cur][nf]);
        }
        return ready_next;
    };

    int g = 0;
    uint32_t rdy = 0;
#pragma unroll 1
    for (int i = 0; i < ntiles; i++) {
        int tile = cta + i * gsz;
        int nt = tile & 7, mt = (tile >> 3) & 63, pc = tile >> 9;

#pragma unroll
        for (int ii = 0; ii < 4; ii++)
#pragma unroll
            for (int j = 0; j < 4; j++)
#pragma unroll
                for (int v = 0; v < 4; v++) { acc0[ii][j][v] = 0.0f; acc1[ii][j][v] = 0.0f; }

        // segment 0: phases 0,1 -> acc0 (accA)
#pragma unroll 1
        for (int l = 0; l < 16; l++) rdy = do_kt(g + l, acc0, rdy);
        // segment 1: phases 2,3 -> acc1 (accB)
#pragma unroll 1
        for (int l = 16; l < 32; l++) rdy = do_kt(g + l, acc1, rdy);

        float bia[4][2];
#pragma unroll
        for (int nf = 0; nf < 4; nf++) {
            int coll = wn * 32 + nf * 8 + (lane & 3) * 2;
            bia[nf][0] = __ldg(brr + nt * BN + coll);
            bia[nf][1] = __ldg(brr + nt * BN + coll + 1);
        }

        // mid epilogue: out_first = A - B + bias; then acc0 = A + B (T)
        {
            size_t colR = (size_t)pc * 2048 + nt * BN;
#pragma unroll
            for (int nf = 0; nf < 4; nf++) {
                int coll = wn * 32 + nf * 8 + (lane & 3) * 2;
#pragma unroll
                for (int mf = 0; mf < 4; mf++) {
                    size_t row0 = (size_t)mt * BM + wm * 64 + mf * 16 + (lane >> 2);
#pragma unroll
                    for (int h = 0; h < 2; h++) {
                        int v0 = h * 2, v1 = h * 2 + 1;
                        float2 vr = make_float2(acc0[mf][nf][v0] - acc1[mf][nf][v0] + bia[nf][0],
                                                acc0[mf][nf][v1] - acc1[mf][nf][v1] + bia[nf][1]);
                        stcs2(out + (row0 + h * 8) * FEAT + colR + coll, vr);
                    }
                }
            }
#pragma unroll
            for (int ii = 0; ii < 4; ii++)
#pragma unroll
                for (int j = 0; j < 4; j++)
#pragma unroll
                    for (int v = 0; v < 4; v++) {
                        acc0[ii][j][v] += acc1[ii][j][v];   // T = A + B
                        acc1[ii][j][v] = 0.0f;
                    }
        }

        // segment 2: phases 4,5 -> acc1 (accC)
#pragma unroll 1
        for (int l = 32; l < 48; l++) rdy = do_kt(g + l, acc1, rdy);

        // final epilogue: out_second = C - T + bias
        {
            size_t colR = (size_t)pc * 2048 + nt * BN + 1024;
#pragma unroll
            for (int nf = 0; nf < 4; nf++) {
                int coll = wn * 32 + nf * 8 + (lane & 3) * 2;
#pragma unroll
                for (int mf = 0; mf < 4; mf++) {
                    size_t row0 = (size_t)mt * BM + wm * 64 + mf * 16 + (lane >> 2);
#pragma unroll
                    for (int h = 0; h < 2; h++) {
                        int v0 = h * 2, v1 = h * 2 + 1;
                        float2 vi = make_float2(acc1[mf][nf][v0] - acc0[mf][nf][v0] + bia[nf][0],
                                                acc1[mf][nf][v1] - acc0[mf][nf][v1] + bia[nf][1]);
                        stcs2(out + (row0 + h * 8) * FEAT + colR + coll, vi);
                    }
                }
            }
        }
        g += IT_PER_TILE;
    }
}

// ---------------- launch ----------------
extern "C" void kernel_launch(void* const* d_in, const int* in_sizes, int n_in,
                              void* d_out, int out_size) {
    const float* x   = (const float*)d_in[0];
    const float* wrr = (const float*)d_in[1];
    const float* wri = (const float*)d_in[2];
    const float* wrj = (const float*)d_in[3];
    const float* wrk = (const float*)d_in[4];
    const float* brr = (const float*)d_in[5];
    float* out = (float*)d_out;

    k_pack<<<XP_BLOCKS + WP_BLOCKS, 256>>>(x, wrr, wri, wrj, wrk);

    static int g_sms = -1;
    if (g_sms < 0) {
        cudaDeviceProp prop;
        cudaGetDeviceProperties(&prop, 0);
        g_sms = prop.multiProcessorCount;
        cudaFuncSetAttribute(k_qdense, cudaFuncAttributeMaxDynamicSharedMemorySize, SMEM_TOTAL);
    }
    k_qdense<<<g_sms, 256, SMEM_TOTAL>>>(brr, out, g_sms);
}